// round 4
// baseline (speedup 1.0000x reference)
#include <cuda_runtime.h>
#include <stdint.h>

#define NN 4096
#define H 64
#define FIN 8
#define SPLIT 8
#define BM 128
#define BK 32
#define KCHUNK (NN / SPLIT) /* 512 */
#define MROWS 16

// -------- persistent scratch (no allocations allowed) --------
__device__ float g_h0[NN * H];
__device__ float g_h1[NN * H];
__device__ float g_part[SPLIT][NN * H];
__device__ float g_si[NN];
__device__ float g_sj[NN];

// -------- packed fp32x2 helpers (B300: FFMA2 only reachable via PTX) --------
__device__ __forceinline__ unsigned long long f32x2_dup(float x) {
    unsigned long long r;
    asm("mov.b64 %0, {%1, %2};" : "=l"(r) : "r"(__float_as_int(x)), "r"(__float_as_int(x)));
    return r;
}
__device__ __forceinline__ void f32x2_fma(unsigned long long& d,
                                          unsigned long long a,
                                          unsigned long long b) {
    asm("fma.rn.f32x2 %0, %1, %2, %0;" : "+l"(d) : "l"(a), "l"(b));
}
__device__ __forceinline__ float f32x2_lo(unsigned long long v) {
    return __int_as_float((int)(unsigned)(v & 0xffffffffull));
}
__device__ __forceinline__ float f32x2_hi(unsigned long long v) {
    return __int_as_float((int)(unsigned)(v >> 32));
}

// ============================================================
// Encoder: h0 = relu(X @ W_enc^T + b_enc)    [4096,8]x[8,64]
// ============================================================
__global__ void enc_kernel(const float* __restrict__ X,
                           const float* __restrict__ We,
                           const float* __restrict__ be,
                           float* __restrict__ hout) {
    __shared__ float Ws[H][FIN];
    __shared__ float bs[H];
    int tid = threadIdx.x;
    // FIX (R2): H*FIN = 512 > blockDim 256 -> must loop, not mask.
    for (int i = tid; i < H * FIN; i += 256) Ws[i / FIN][i % FIN] = We[i];
    if (tid < H) bs[tid] = be[tid];
    __syncthreads();
    int idx = blockIdx.x * 256 + tid;
    int i = idx >> 6, j = idx & 63;
    const float* xr = X + i * FIN;
    float acc = bs[j];
#pragma unroll
    for (int f = 0; f < FIN; f++) acc += xr[f] * Ws[j][f];
    hout[idx] = fmaxf(acc, 0.0f);
}

// ============================================================
// Split-K GEMM: part[s] = A[:, s*512:(s+1)*512] @ h[s*512:...]
// grid (32, 8), 256 threads. Tile 128x64, BK=32.
// Micro-tile per thread: 8 rows (as 4 f32x2 row-pairs) x 4 cols.
// ============================================================
__global__ __launch_bounds__(256, 2)
void gemm_kernel(const float* __restrict__ A, const float* __restrict__ h) {
    __shared__ __align__(16) float AsT[BK][BM + 4];  // [kk][row], stride 132
    __shared__ __align__(16) float Hs[BK][H];        // [kk][col]
    const int tid = threadIdx.x;
    const int mbase = blockIdx.x * BM;
    const int kbase = blockIdx.y * KCHUNK;
    const int tx = tid & 15;   // col group: cols tx*4..tx*4+3
    const int ty = tid >> 4;   // row group: rows ty*8..ty*8+7

    unsigned long long acc[4][4];
#pragma unroll
    for (int p = 0; p < 4; p++)
#pragma unroll
        for (int c = 0; c < 4; c++) acc[p][c] = 0ull;

#pragma unroll 1
    for (int kt = 0; kt < KCHUNK; kt += BK) {
        const int k0 = kbase + kt;
        // A tile 128x32, transposed into AsT[kk][row]
#pragma unroll
        for (int i = 0; i < 16; i++) {
            int idx = tid + i * 256;
            int row = idx >> 5, kk = idx & 31;
            AsT[kk][row] = A[(size_t)(mbase + row) * NN + (k0 + kk)];
        }
        // H tile 32x64
#pragma unroll
        for (int i = 0; i < 8; i++) {
            int idx = tid + i * 256;
            int kk = idx >> 6, col = idx & 63;
            Hs[kk][col] = h[(k0 + kk) * H + col];
        }
        __syncthreads();
#pragma unroll
        for (int kk = 0; kk < BK; kk++) {
            const ulonglong2* ap =
                reinterpret_cast<const ulonglong2*>(&AsT[kk][ty * 8]);
            ulonglong2 a01 = ap[0];   // rows (0,1) and (2,3) of this thread
            ulonglong2 a23 = ap[1];   // rows (4,5) and (6,7)
            float4 b4 = *reinterpret_cast<const float4*>(&Hs[kk][tx * 4]);
            unsigned long long b0 = f32x2_dup(b4.x);
            unsigned long long b1 = f32x2_dup(b4.y);
            unsigned long long b2 = f32x2_dup(b4.z);
            unsigned long long b3 = f32x2_dup(b4.w);
            f32x2_fma(acc[0][0], a01.x, b0);
            f32x2_fma(acc[0][1], a01.x, b1);
            f32x2_fma(acc[0][2], a01.x, b2);
            f32x2_fma(acc[0][3], a01.x, b3);
            f32x2_fma(acc[1][0], a01.y, b0);
            f32x2_fma(acc[1][1], a01.y, b1);
            f32x2_fma(acc[1][2], a01.y, b2);
            f32x2_fma(acc[1][3], a01.y, b3);
            f32x2_fma(acc[2][0], a23.x, b0);
            f32x2_fma(acc[2][1], a23.x, b1);
            f32x2_fma(acc[2][2], a23.x, b2);
            f32x2_fma(acc[2][3], a23.x, b3);
            f32x2_fma(acc[3][0], a23.y, b0);
            f32x2_fma(acc[3][1], a23.y, b1);
            f32x2_fma(acc[3][2], a23.y, b2);
            f32x2_fma(acc[3][3], a23.y, b3);
        }
        __syncthreads();
    }

    float* out = g_part[blockIdx.y];
#pragma unroll
    for (int p = 0; p < 4; p++) {
        int r0 = mbase + ty * 8 + 2 * p;
#pragma unroll
        for (int c = 0; c < 4; c++) {
            int col = tx * 4 + c;
            out[(size_t)r0 * H + col]       = f32x2_lo(acc[p][c]);
            out[(size_t)(r0 + 1) * H + col] = f32x2_hi(acc[p][c]);
        }
    }
}

// ============================================================
// MLP: hout = relu([h, sum_s part_s] @ W^T + b)
// grid 256 blocks x 256 threads; 16 rows/block; W staged in smem.
// ============================================================
__global__ __launch_bounds__(256)
void mlp_kernel(const float* __restrict__ hin, const float* __restrict__ W,
                const float* __restrict__ b, float* __restrict__ hout) {
    __shared__ float Ws[H][2 * H + 1];   // stride 129 -> conflict-free
    __shared__ float h_s[MROWS][H];
    __shared__ float hn_s[MROWS][H];
    const int tid = threadIdx.x;
    const int rbase = blockIdx.x * MROWS;

    for (int i = tid; i < H * 2 * H; i += 256)
        Ws[i / (2 * H)][i % (2 * H)] = W[i];
    for (int i = tid; i < MROWS * H; i += 256) {
        int r = i >> 6, c = i & 63;
        h_s[r][c] = hin[(rbase + r) * H + c];
        float s = 0.0f;
#pragma unroll
        for (int p = 0; p < SPLIT; p++) s += g_part[p][(rbase + r) * H + c];
        hn_s[r][c] = s;
    }
    __syncthreads();

    const int col = tid & 63;
    const int rg = tid >> 6;  // 0..3
    const float bias = b[col];
#pragma unroll
    for (int rr = 0; rr < MROWS / 4; rr++) {
        int r = rg * (MROWS / 4) + rr;
        float acc = bias;
#pragma unroll
        for (int c = 0; c < H; c++)
            acc += h_s[r][c] * Ws[col][c] + hn_s[r][c] * Ws[col][H + c];
        hout[(rbase + r) * H + col] = fmaxf(acc, 0.0f);
    }
}

// ============================================================
// s_i / s_j projections (b_edge folded into s_i)
// ============================================================
__global__ void sisj_kernel(const float* __restrict__ h,
                            const float* __restrict__ Wedge,
                            const float* __restrict__ bedge) {
    __shared__ float w[2 * H];
    int tid = threadIdx.x;
    if (tid < 2 * H) w[tid] = Wedge[tid];
    __syncthreads();
    int i = blockIdx.x * 256 + tid;
    float a = 0.0f, bb = 0.0f;
#pragma unroll
    for (int c = 0; c < H; c++) {
        float hv = h[i * H + c];
        a += hv * w[c];
        bb += hv * w[H + c];
    }
    g_si[i] = a + bedge[0];
    g_sj[i] = bb;
}

// ============================================================
// scores[i][j] = s_i[i] + s_j[j] + b_edge, diag zeroed. float4 stores.
// ============================================================
__global__ void scores_kernel(float* __restrict__ out) {
    int idx = blockIdx.x * 256 + threadIdx.x;  // NN*NN/4 total
    int i = idx >> 10;                         // NN/4 = 1024 float4 per row
    int j4 = (idx & 1023) << 2;
    float si = g_si[i];
    float4 sj = *reinterpret_cast<const float4*>(&g_sj[j4]);
    float4 v = make_float4(si + sj.x, si + sj.y, si + sj.z, si + sj.w);
    int d = i - j4;
    if (d >= 0 && d < 4) ((float*)&v)[d] = 0.0f;
    reinterpret_cast<float4*>(out)[idx] = v;
}

// ============================================================
extern "C" void kernel_launch(void* const* d_in, const int* in_sizes, int n_in,
                              void* d_out, int out_size) {
    const float* X     = (const float*)d_in[0];
    const float* Adj   = (const float*)d_in[1];
    const float* We    = (const float*)d_in[2];
    const float* be    = (const float*)d_in[3];
    const float* Wl[3] = {(const float*)d_in[4], (const float*)d_in[6],
                          (const float*)d_in[8]};
    const float* bl[3] = {(const float*)d_in[5], (const float*)d_in[7],
                          (const float*)d_in[9]};
    const float* Wedge = (const float*)d_in[10];
    const float* bedge = (const float*)d_in[11];
    float* out = (float*)d_out;

    float *ph0 = nullptr, *ph1 = nullptr;
    cudaGetSymbolAddress((void**)&ph0, g_h0);
    cudaGetSymbolAddress((void**)&ph1, g_h1);

    enc_kernel<<<NN * H / 256, 256>>>(X, We, be, ph0);

    float* hcur = ph0;
    float* hnext = ph1;
    for (int l = 0; l < 3; l++) {
        gemm_kernel<<<dim3(NN / BM, SPLIT), 256>>>(Adj, hcur);
        mlp_kernel<<<NN / MROWS, 256>>>(hcur, Wl[l], bl[l], hnext);
        float* t = hcur; hcur = hnext; hnext = t;
    }

    sisj_kernel<<<NN / 256, 256>>>(hcur, Wedge, bedge);
    scores_kernel<<<(NN / 4) * NN / 256, 256>>>(out);
}

// round 7
// speedup vs baseline: 1.6900x; 1.6900x over previous
#include <cuda_runtime.h>
#include <cuda_bf16.h>
#include <stdint.h>

#define NN 4096
#define H 64
#define FIN 8
#define SPLITK 8
#define KCHUNK (NN / SPLITK)   /* 512 */
#define NCHUNK (KCHUNK / 64)   /* 8 chunks of K=64 */
#define MROWS 16

// -------- persistent scratch (no device allocations allowed) --------
__device__ __nv_bfloat16 g_Ahi[(size_t)NN * NN];
__device__ __nv_bfloat16 g_Alo[(size_t)NN * NN];
__device__ __nv_bfloat16 g_hThi[(size_t)H * NN];   // h^T: [n][k], K-major
__device__ __nv_bfloat16 g_hTlo[(size_t)H * NN];
__device__ float g_h0[NN * H];
__device__ float g_h1[NN * H];
__device__ float g_part[SPLITK][NN * H];
__device__ float g_si[NN];
__device__ float g_sj[NN];

// ---------------- helpers ----------------
__device__ __forceinline__ uint32_t smem_u32(const void* p) {
    uint32_t a;
    asm("{ .reg .u64 t; cvta.to.shared.u64 t, %1; cvt.u32.u64 %0, t; }"
        : "=r"(a) : "l"(p));
    return a;
}
#define SW128(off) ((off) ^ (((off) >> 3) & 0x70))
#define CP_ASYNC16(dst, src) \
    asm volatile("cp.async.cg.shared.global [%0], [%1], 16;" :: "r"(dst), "l"(src))
#define CP_COMMIT() asm volatile("cp.async.commit_group;" ::: "memory")
#define CP_WAIT(n)  asm volatile("cp.async.wait_group %0;" :: "n"(n) : "memory")

#define LDSM_X4(r0, r1, r2, r3, addr) \
    asm volatile("ldmatrix.sync.aligned.m8n8.x4.shared.b16 {%0,%1,%2,%3}, [%4];" \
        : "=r"(r0), "=r"(r1), "=r"(r2), "=r"(r3) : "r"(addr))

#define MMA_BF16(c, a, b0v, b1v) \
    asm volatile("mma.sync.aligned.m16n8k16.row.col.f32.bf16.bf16.f32 " \
        "{%0,%1,%2,%3}, {%4,%5,%6,%7}, {%8,%9}, {%0,%1,%2,%3};" \
        : "+f"((c)[0]), "+f"((c)[1]), "+f"((c)[2]), "+f"((c)[3]) \
        : "r"((a)[0]), "r"((a)[1]), "r"((a)[2]), "r"((a)[3]), "r"(b0v), "r"(b1v))

// ============================================================
// convA: A fp32 -> (bf16 hi, bf16 lo residual), once per launch
// ============================================================
__global__ void convA_kernel(const float* __restrict__ A) {
    size_t t = (size_t)blockIdx.x * 256 + threadIdx.x;   // one per 8 floats
    const float4* a4 = reinterpret_cast<const float4*>(A);
    float4 a = a4[2 * t], b = a4[2 * t + 1];
    float v[8] = {a.x, a.y, a.z, a.w, b.x, b.y, b.z, b.w};
    __nv_bfloat16 hi[8], lo[8];
#pragma unroll
    for (int e = 0; e < 8; e++) {
        hi[e] = __float2bfloat16_rn(v[e]);
        lo[e] = __float2bfloat16_rn(v[e] - __bfloat162float(hi[e]));
    }
    reinterpret_cast<uint4*>(g_Ahi)[t] = *reinterpret_cast<uint4*>(hi);
    reinterpret_cast<uint4*>(g_Alo)[t] = *reinterpret_cast<uint4*>(lo);
}

// ============================================================
// convH: h [NN,H] fp32 -> hT hi/lo [H,NN] bf16 (transpose + split)
// ============================================================
__global__ void convH_kernel(const float* __restrict__ h) {
    __shared__ float tile[64][65];
    int tid = threadIdx.x;
    int kb = blockIdx.x * 64;
#pragma unroll
    for (int it = 0; it < 16; it++) {
        int idx = tid + it * 256;
        int r = idx >> 6, c = idx & 63;
        tile[r][c] = h[(kb + r) * H + c];
    }
    __syncthreads();
#pragma unroll
    for (int it = 0; it < 16; it++) {
        int idx = tid + it * 256;
        int n = idx >> 6, kl = idx & 63;
        float v = tile[kl][n];
        __nv_bfloat16 hi = __float2bfloat16_rn(v);
        __nv_bfloat16 lo = __float2bfloat16_rn(v - __bfloat162float(hi));
        g_hThi[(size_t)n * NN + kb + kl] = hi;
        g_hTlo[(size_t)n * NN + kb + kl] = lo;
    }
}

// ============================================================
// Encoder: h0 = relu(X @ W_enc^T + b_enc)
// ============================================================
__global__ void enc_kernel(const float* __restrict__ X,
                           const float* __restrict__ We,
                           const float* __restrict__ be,
                           float* __restrict__ hout) {
    __shared__ float Ws[H][FIN];
    __shared__ float bs[H];
    int tid = threadIdx.x;
    for (int i = tid; i < H * FIN; i += 256) Ws[i / FIN][i % FIN] = We[i];
    if (tid < H) bs[tid] = be[tid];
    __syncthreads();
    int idx = blockIdx.x * 256 + tid;
    int i = idx >> 6, j = idx & 63;
    const float* xr = X + i * FIN;
    float acc = bs[j];
#pragma unroll
    for (int f = 0; f < FIN; f++) acc += xr[f] * Ws[j][f];
    hout[idx] = fmaxf(acc, 0.0f);
}

// ============================================================
// bf16x2 HMMA GEMM: part[sk] = A[:, sk*512:+512] @ h[sk*512:+512]
// A ~ Ahi+Alo, B ~ Bhi+Blo; acc += Ahi*Bhi + Ahi*Blo + Alo*Bhi (fp32).
// grid (32, 8) x 256 thr. CTA tile 128x64, BK=64, 2-stage cp.async.
// Warp grid 2x4; warp tile 64x16 (4 x m16, 2 x n8).
// ============================================================
#define AHI_OFF 0
#define ALO_OFF 16384
#define BHI_OFF 32768
#define BLO_OFF 40960
#define STAGE_BYTES 49152       /* 16+16+8+8 KB */
#define SMEM_TOTAL (2 * STAGE_BYTES)   /* 98304 */

__device__ __forceinline__ void load_chunk(uint32_t smem_base, int s, int k0,
                                           int tid, int mbase) {
    const char* AbH = reinterpret_cast<const char*>(g_Ahi);
    const char* AbL = reinterpret_cast<const char*>(g_Alo);
    const char* HbH = reinterpret_cast<const char*>(g_hThi);
    const char* HbL = reinterpret_cast<const char*>(g_hTlo);
    uint32_t base = smem_base + s * STAGE_BYTES;
#pragma unroll
    for (int it = 0; it < 4; it++) {                 // A: 128 rows x 128B
        int c = tid + it * 256;
        int row = c >> 3, j = c & 7;
        uint32_t sw = SW128((uint32_t)(row * 128 + j * 16));
        size_t gb = ((size_t)(mbase + row) * NN + k0) * 2 + j * 16;
        CP_ASYNC16(base + AHI_OFF + sw, AbH + gb);
        CP_ASYNC16(base + ALO_OFF + sw, AbL + gb);
    }
#pragma unroll
    for (int it = 0; it < 2; it++) {                 // B: 64 n-rows x 128B
        int c = tid + it * 256;
        int n = c >> 3, j = c & 7;
        uint32_t sw = SW128((uint32_t)(n * 128 + j * 16));
        size_t gb = ((size_t)n * NN + k0) * 2 + j * 16;
        CP_ASYNC16(base + BHI_OFF + sw, HbH + gb);
        CP_ASYNC16(base + BLO_OFF + sw, HbL + gb);
    }
    CP_COMMIT();
}

__global__ __launch_bounds__(256, 2)
void gemm_mma_kernel() {
    extern __shared__ __align__(1024) char smem[];
    const uint32_t smem_base = smem_u32(smem);
    const int tid = threadIdx.x;
    const int wid = tid >> 5;
    const int lane = tid & 31;
    const int warp_m = wid >> 2;        // 0..1 -> 64 rows each
    const int warp_n = wid & 3;         // 0..3 -> 16 cols each
    const int mbase = blockIdx.x * 128;
    const int kbase = blockIdx.y * KCHUNK;

    float acc[4][2][4];
#pragma unroll
    for (int mt = 0; mt < 4; mt++)
#pragma unroll
        for (int nt = 0; nt < 2; nt++)
#pragma unroll
            for (int e = 0; e < 4; e++) acc[mt][nt][e] = 0.0f;

    // ldmatrix lane addressing (constant per thread)
    const int a_row = lane & 15;
    const int a_khalf = (lane >> 4) * 16;
    const int b_m = lane >> 3;
    const int b_r = lane & 7;
    const int b_n = ((b_m >> 1) << 3) + b_r;
    const int b_khalf = (b_m & 1) * 16;

    load_chunk(smem_base, 0, kbase, tid, mbase);

#pragma unroll 1
    for (int i = 0; i < NCHUNK; i++) {
        const int s = i & 1;
        if (i + 1 < NCHUNK) {
            load_chunk(smem_base, (i + 1) & 1, kbase + (i + 1) * 64, tid, mbase);
            CP_WAIT(1);
        } else {
            CP_WAIT(0);
        }
        __syncthreads();

        const uint32_t base = smem_base + s * STAGE_BYTES;
#pragma unroll
        for (int ks = 0; ks < 4; ks++) {
            uint32_t boff = SW128((uint32_t)((warp_n * 16 + b_n) * 128 +
                                             ks * 32 + b_khalf));
            uint32_t bh[4], bl[4];
            LDSM_X4(bh[0], bh[1], bh[2], bh[3], base + BHI_OFF + boff);
            LDSM_X4(bl[0], bl[1], bl[2], bl[3], base + BLO_OFF + boff);
#pragma unroll
            for (int mt = 0; mt < 4; mt++) {
                uint32_t aoff = SW128((uint32_t)(
                    (warp_m * 64 + mt * 16 + a_row) * 128 + ks * 32 + a_khalf));
                uint32_t ah[4], al[4];
                LDSM_X4(ah[0], ah[1], ah[2], ah[3], base + AHI_OFF + aoff);
                LDSM_X4(al[0], al[1], al[2], al[3], base + ALO_OFF + aoff);
                MMA_BF16(acc[mt][0], ah, bh[0], bh[1]);
                MMA_BF16(acc[mt][1], ah, bh[2], bh[3]);
                MMA_BF16(acc[mt][0], ah, bl[0], bl[1]);
                MMA_BF16(acc[mt][1], ah, bl[2], bl[3]);
                MMA_BF16(acc[mt][0], al, bh[0], bh[1]);
                MMA_BF16(acc[mt][1], al, bh[2], bh[3]);
            }
        }
        __syncthreads();
    }

    // epilogue: write 64x16 warp tile to g_part[blockIdx.y]
    float* out = g_part[blockIdx.y];
    const int r0 = mbase + warp_m * 64 + (lane >> 2);
    const int c0 = warp_n * 16 + (lane & 3) * 2;
#pragma unroll
    for (int mt = 0; mt < 4; mt++) {
#pragma unroll
        for (int nt = 0; nt < 2; nt++) {
            int col = c0 + nt * 8;
            float2 lo = make_float2(acc[mt][nt][0], acc[mt][nt][1]);
            float2 hi = make_float2(acc[mt][nt][2], acc[mt][nt][3]);
            *reinterpret_cast<float2*>(&out[(size_t)(r0 + mt * 16) * H + col]) = lo;
            *reinterpret_cast<float2*>(&out[(size_t)(r0 + mt * 16 + 8) * H + col]) = hi;
        }
    }
}

// ============================================================
// MLP: hout = relu([h, sum_sk part_sk] @ W^T + b)
// ============================================================
__global__ __launch_bounds__(256)
void mlp_kernel(const float* __restrict__ hin, const float* __restrict__ W,
                const float* __restrict__ b, float* __restrict__ hout) {
    __shared__ float Ws[H][2 * H + 1];
    __shared__ float h_s[MROWS][H];
    __shared__ float hn_s[MROWS][H];
    const int tid = threadIdx.x;
    const int rbase = blockIdx.x * MROWS;

    for (int i = tid; i < H * 2 * H; i += 256)
        Ws[i / (2 * H)][i % (2 * H)] = W[i];
    for (int i = tid; i < MROWS * H; i += 256) {
        int r = i >> 6, c = i & 63;
        h_s[r][c] = hin[(rbase + r) * H + c];
        float s = 0.0f;
#pragma unroll
        for (int p = 0; p < SPLITK; p++) s += g_part[p][(rbase + r) * H + c];
        hn_s[r][c] = s;
    }
    __syncthreads();

    const int col = tid & 63;
    const int rg = tid >> 6;
    const float bias = b[col];
#pragma unroll
    for (int rr = 0; rr < MROWS / 4; rr++) {
        int r = rg * (MROWS / 4) + rr;
        float acc = bias;
#pragma unroll
        for (int c = 0; c < H; c++)
            acc += h_s[r][c] * Ws[col][c] + hn_s[r][c] * Ws[col][H + c];
        hout[(rbase + r) * H + col] = fmaxf(acc, 0.0f);
    }
}

// ============================================================
// s_i / s_j projections (b_edge folded into s_i)
// ============================================================
__global__ void sisj_kernel(const float* __restrict__ h,
                            const float* __restrict__ Wedge,
                            const float* __restrict__ bedge) {
    __shared__ float w[2 * H];
    int tid = threadIdx.x;
    if (tid < 2 * H) w[tid] = Wedge[tid];
    __syncthreads();
    int i = blockIdx.x * 256 + tid;
    float a = 0.0f, bb = 0.0f;
#pragma unroll
    for (int c = 0; c < H; c++) {
        float hv = h[i * H + c];
        a += hv * w[c];
        bb += hv * w[H + c];
    }
    g_si[i] = a + bedge[0];
    g_sj[i] = bb;
}

// ============================================================
// scores[i][j] = s_i[i] + s_j[j], diag zeroed. float4 stores.
// ============================================================
__global__ void scores_kernel(float* __restrict__ out) {
    int idx = blockIdx.x * 256 + threadIdx.x;
    int i = idx >> 10;
    int j4 = (idx & 1023) << 2;
    float si = g_si[i];
    float4 sj = *reinterpret_cast<const float4*>(&g_sj[j4]);
    float4 v = make_float4(si + sj.x, si + sj.y, si + sj.z, si + sj.w);
    int d = i - j4;
    if (d >= 0 && d < 4) ((float*)&v)[d] = 0.0f;
    reinterpret_cast<float4*>(out)[idx] = v;
}

// ============================================================
extern "C" void kernel_launch(void* const* d_in, const int* in_sizes, int n_in,
                              void* d_out, int out_size) {
    const float* X     = (const float*)d_in[0];
    const float* Adj   = (const float*)d_in[1];
    const float* We    = (const float*)d_in[2];
    const float* be    = (const float*)d_in[3];
    const float* Wl[3] = {(const float*)d_in[4], (const float*)d_in[6],
                          (const float*)d_in[8]};
    const float* bl[3] = {(const float*)d_in[5], (const float*)d_in[7],
                          (const float*)d_in[9]};
    const float* Wedge = (const float*)d_in[10];
    const float* bedge = (const float*)d_in[11];
    float* out = (float*)d_out;

    cudaFuncSetAttribute(gemm_mma_kernel,
                         cudaFuncAttributeMaxDynamicSharedMemorySize, SMEM_TOTAL);

    float *ph0 = nullptr, *ph1 = nullptr;
    cudaGetSymbolAddress((void**)&ph0, g_h0);
    cudaGetSymbolAddress((void**)&ph1, g_h1);

    convA_kernel<<<(NN * NN / 8) / 256, 256>>>(Adj);
    enc_kernel<<<NN * H / 256, 256>>>(X, We, be, ph0);

    float* hcur = ph0;
    float* hnext = ph1;
    for (int l = 0; l < 3; l++) {
        convH_kernel<<<NN / 64, 256>>>(hcur);
        gemm_mma_kernel<<<dim3(NN / 128, SPLITK), 256, SMEM_TOTAL>>>();
        mlp_kernel<<<NN / MROWS, 256>>>(hcur, Wl[l], bl[l], hnext);
        float* t = hcur; hcur = hnext; hnext = t;
    }

    sisj_kernel<<<NN / 256, 256>>>(hcur, Wedge, bedge);
    scores_kernel<<<(NN / 4) * NN / 256, 256>>>(out);
}

// round 9
// speedup vs baseline: 2.3916x; 1.4151x over previous
#include <cuda_runtime.h>
#include <cuda_fp16.h>
#include <stdint.h>

#define NN 4096
#define H 64
#define FIN 8
#define SPLITK 8
#define KCHUNK (NN / SPLITK)   /* 512 */
#define NCHUNK (KCHUNK / 64)   /* 8 chunks of K=64 */
#define MROWS 16
#define HSCL  (1.0f / 1024.0f)   /* exact pow2: keeps h^T inside fp16 range */
#define HUNSCL 1024.0f

// -------- persistent scratch (no device allocations allowed) --------
__device__ __half g_Af[(size_t)NN * NN];     // A in fp16, row-major
__device__ __half g_hTf[(size_t)H * NN];     // (h*HSCL)^T fp16: [n][k], K-major
__device__ float g_h0[NN * H];
__device__ float g_h1[NN * H];
__device__ float g_part[SPLITK][NN * H];
__device__ float g_si[NN];
__device__ float g_sj[NN];

// ---------------- helpers ----------------
__device__ __forceinline__ uint32_t smem_u32(const void* p) {
    uint32_t a;
    asm("{ .reg .u64 t; cvta.to.shared.u64 t, %1; cvt.u32.u64 %0, t; }"
        : "=r"(a) : "l"(p));
    return a;
}
#define SW128(off) ((off) ^ (((off) >> 3) & 0x70))
#define CP_ASYNC16(dst, src) \
    asm volatile("cp.async.cg.shared.global [%0], [%1], 16;" :: "r"(dst), "l"(src))
#define CP_COMMIT() asm volatile("cp.async.commit_group;" ::: "memory")
#define CP_WAIT(n)  asm volatile("cp.async.wait_group %0;" :: "n"(n) : "memory")

#define LDSM_X4(r0, r1, r2, r3, addr) \
    asm volatile("ldmatrix.sync.aligned.m8n8.x4.shared.b16 {%0,%1,%2,%3}, [%4];" \
        : "=r"(r0), "=r"(r1), "=r"(r2), "=r"(r3) : "r"(addr))

#define MMA_F16(c, a, b0v, b1v) \
    asm volatile("mma.sync.aligned.m16n8k16.row.col.f32.f16.f16.f32 " \
        "{%0,%1,%2,%3}, {%4,%5,%6,%7}, {%8,%9}, {%0,%1,%2,%3};" \
        : "+f"((c)[0]), "+f"((c)[1]), "+f"((c)[2]), "+f"((c)[3]) \
        : "r"((a)[0]), "r"((a)[1]), "r"((a)[2]), "r"((a)[3]), "r"(b0v), "r"(b1v))

// ============================================================
// convA: A fp32 -> fp16 (once per launch; A in [0,1) — safe range)
// ============================================================
__global__ void convA_kernel(const float* __restrict__ A) {
    size_t t = (size_t)blockIdx.x * 256 + threadIdx.x;   // one per 8 floats
    const float4* a4 = reinterpret_cast<const float4*>(A);
    float4 a = a4[2 * t], b = a4[2 * t + 1];
    __half2 p0 = __floats2half2_rn(a.x, a.y);
    __half2 p1 = __floats2half2_rn(a.z, a.w);
    __half2 p2 = __floats2half2_rn(b.x, b.y);
    __half2 p3 = __floats2half2_rn(b.z, b.w);
    uint4 u;
    u.x = *reinterpret_cast<uint32_t*>(&p0);
    u.y = *reinterpret_cast<uint32_t*>(&p1);
    u.z = *reinterpret_cast<uint32_t*>(&p2);
    u.w = *reinterpret_cast<uint32_t*>(&p3);
    reinterpret_cast<uint4*>(g_Af)[t] = u;
}

// ============================================================
// Encoder: h0 = relu(X @ W_enc^T + b_enc); also writes scaled hT fp16.
// Each block: 4 rows x 64 cols.
// ============================================================
__global__ void enc_kernel(const float* __restrict__ X,
                           const float* __restrict__ We,
                           const float* __restrict__ be,
                           float* __restrict__ hout) {
    __shared__ float Ws[H][FIN];
    __shared__ float bs[H];
    __shared__ float hsm[4][64];
    int tid = threadIdx.x;
    for (int i = tid; i < H * FIN; i += 256) Ws[i / FIN][i % FIN] = We[i];
    if (tid < H) bs[tid] = be[tid];
    __syncthreads();
    int idx = blockIdx.x * 256 + tid;
    int i = idx >> 6, j = idx & 63;
    const float* xr = X + i * FIN;
    float acc = bs[j];
#pragma unroll
    for (int f = 0; f < FIN; f++) acc += xr[f] * Ws[j][f];
    float v = fmaxf(acc, 0.0f);
    hout[idx] = v;
    hsm[tid >> 6][j] = v;
    __syncthreads();
    // transpose-write scaled hT fp16: n = tid>>2 (0..63), kl = tid&3 (0..3)
    int n = tid >> 2, kl = tid & 3;
    int kb = blockIdx.x * 4;
    g_hTf[(size_t)n * NN + kb + kl] = __float2half_rn(hsm[kl][n] * HSCL);
}

// ============================================================
// fp16 HMMA GEMM: part[sk] = A[:, sk*512:+512] @ (h*HSCL)[sk*512:+512]
// grid (32, 8) x 256 thr. CTA tile 128x64, BK=64, 2-stage cp.async.
// Warp grid 2x4; warp tile 64x16 (4 x m16, 2 x n8). fp32 accum.
// ============================================================
#define STAGE_BYTES 24576       /* 16KB A + 8KB B */
#define B_SOFF 16384
#define SMEM_TOTAL (2 * STAGE_BYTES)   /* 49152 */

__device__ __forceinline__ void load_chunk(uint32_t smem_base, int s, int k0,
                                           int tid, int mbase) {
    const char* Ab = reinterpret_cast<const char*>(g_Af);
    const char* Hb = reinterpret_cast<const char*>(g_hTf);
    uint32_t abase = smem_base + s * STAGE_BYTES;
    uint32_t bbase = smem_base + B_SOFF + s * STAGE_BYTES;
#pragma unroll
    for (int it = 0; it < 4; it++) {                 // A: 128 rows x 128B
        int c = tid + it * 256;
        int row = c >> 3, j = c & 7;
        uint32_t off = (uint32_t)(row * 128 + j * 16);
        const char* src = Ab + ((size_t)(mbase + row) * NN + k0) * 2 + j * 16;
        CP_ASYNC16(abase + SW128(off), src);
    }
#pragma unroll
    for (int it = 0; it < 2; it++) {                 // B: 64 n-rows x 128B
        int c = tid + it * 256;
        int n = c >> 3, j = c & 7;
        uint32_t off = (uint32_t)(n * 128 + j * 16);
        const char* src = Hb + ((size_t)n * NN + k0) * 2 + j * 16;
        CP_ASYNC16(bbase + SW128(off), src);
    }
    CP_COMMIT();
}

__global__ __launch_bounds__(256, 2)
void gemm_mma_kernel() {
    extern __shared__ __align__(1024) char smem[];
    const uint32_t smem_base = smem_u32(smem);
    const int tid = threadIdx.x;
    const int wid = tid >> 5;
    const int lane = tid & 31;
    const int warp_m = wid >> 2;        // 0..1 -> 64 rows each
    const int warp_n = wid & 3;         // 0..3 -> 16 cols each
    const int mbase = blockIdx.x * 128;
    const int kbase = blockIdx.y * KCHUNK;

    float acc[4][2][4];
#pragma unroll
    for (int mt = 0; mt < 4; mt++)
#pragma unroll
        for (int nt = 0; nt < 2; nt++)
#pragma unroll
            for (int e = 0; e < 4; e++) acc[mt][nt][e] = 0.0f;

    // ldmatrix lane addressing (constant per thread)
    const int a_row = lane & 15;
    const int a_khalf = (lane >> 4) * 16;
    const int b_m = lane >> 3;
    const int b_r = lane & 7;
    const int b_n = ((b_m >> 1) << 3) + b_r;
    const int b_khalf = (b_m & 1) * 16;

    load_chunk(smem_base, 0, kbase, tid, mbase);

#pragma unroll 1
    for (int i = 0; i < NCHUNK; i++) {
        const int s = i & 1;
        if (i + 1 < NCHUNK) {
            load_chunk(smem_base, (i + 1) & 1, kbase + (i + 1) * 64, tid, mbase);
            CP_WAIT(1);
        } else {
            CP_WAIT(0);
        }
        __syncthreads();

        const uint32_t abase = smem_base + s * STAGE_BYTES;
        const uint32_t bbase = smem_base + B_SOFF + s * STAGE_BYTES;
#pragma unroll
        for (int ks = 0; ks < 4; ks++) {
            uint32_t b[4];
            {
                uint32_t off = (uint32_t)((warp_n * 16 + b_n) * 128 +
                                          ks * 32 + b_khalf);
                LDSM_X4(b[0], b[1], b[2], b[3], bbase + SW128(off));
            }
#pragma unroll
            for (int mt = 0; mt < 4; mt++) {
                uint32_t a[4];
                uint32_t off = (uint32_t)((warp_m * 64 + mt * 16 + a_row) * 128 +
                                          ks * 32 + a_khalf);
                LDSM_X4(a[0], a[1], a[2], a[3], abase + SW128(off));
                MMA_F16(acc[mt][0], a, b[0], b[1]);
                MMA_F16(acc[mt][1], a, b[2], b[3]);
            }
        }
        __syncthreads();
    }

    // epilogue: write 64x16 warp tile to g_part[blockIdx.y]
    float* out = g_part[blockIdx.y];
    const int r0 = mbase + warp_m * 64 + (lane >> 2);
    const int c0 = warp_n * 16 + (lane & 3) * 2;
#pragma unroll
    for (int mt = 0; mt < 4; mt++) {
#pragma unroll
        for (int nt = 0; nt < 2; nt++) {
            int col = c0 + nt * 8;
            float2 lo = make_float2(acc[mt][nt][0], acc[mt][nt][1]);
            float2 hi = make_float2(acc[mt][nt][2], acc[mt][nt][3]);
            *reinterpret_cast<float2*>(&out[(size_t)(r0 + mt * 16) * H + col]) = lo;
            *reinterpret_cast<float2*>(&out[(size_t)(r0 + mt * 16 + 8) * H + col]) = hi;
        }
    }
}

// ============================================================
// MLP: hout = relu([h, HUNSCL * sum_sk part_sk] @ W^T + b)
// Writes scaled hT fp16 (non-last); last layer computes s_i/s_j.
// ============================================================
__global__ __launch_bounds__(256)
void mlp_kernel(const float* __restrict__ hin, const float* __restrict__ W,
                const float* __restrict__ b, float* __restrict__ hout,
                int last, const float* __restrict__ Wedge,
                const float* __restrict__ bedge) {
    __shared__ float Ws[H][2 * H + 1];
    __shared__ float h_s[MROWS][H];
    __shared__ float hn_s[MROWS][H];
    __shared__ float ho_s[MROWS][H];
    __shared__ float wedge[2 * H];
    const int tid = threadIdx.x;
    const int rbase = blockIdx.x * MROWS;

    for (int i = tid; i < H * 2 * H; i += 256)
        Ws[i / (2 * H)][i % (2 * H)] = W[i];
    if (last && tid < 2 * H) wedge[tid] = Wedge[tid];
    for (int i = tid; i < MROWS * H; i += 256) {
        int r = i >> 6, c = i & 63;
        h_s[r][c] = hin[(rbase + r) * H + c];
        float s = 0.0f;
#pragma unroll
        for (int p = 0; p < SPLITK; p++) s += g_part[p][(rbase + r) * H + c];
        hn_s[r][c] = s * HUNSCL;   // undo fp16 range scaling
    }
    __syncthreads();

    const int col = tid & 63;
    const int rg = tid >> 6;
    const float bias = b[col];
#pragma unroll
    for (int rr = 0; rr < MROWS / 4; rr++) {
        int r = rg * (MROWS / 4) + rr;
        float acc = bias;
#pragma unroll
        for (int c = 0; c < H; c++)
            acc += h_s[r][c] * Ws[col][c] + hn_s[r][c] * Ws[col][H + c];
        float v = fmaxf(acc, 0.0f);
        hout[(rbase + r) * H + col] = v;
        ho_s[r][col] = v;
    }
    __syncthreads();

    if (!last) {
        // transpose-write scaled hT fp16: n = i>>4 (0..63), kl = i&15
        for (int i = tid; i < H * MROWS; i += 256) {
            int n = i >> 4, kl = i & 15;
            g_hTf[(size_t)n * NN + rbase + kl] =
                __float2half_rn(ho_s[kl][n] * HSCL);
        }
    } else {
        // fused s_i / s_j for final h
        if (tid < MROWS) {
            int r = tid;
            float a = 0.0f, bb = 0.0f;
#pragma unroll
            for (int c = 0; c < H; c++) {
                float hv = ho_s[r][c];
                a += hv * wedge[c];
                bb += hv * wedge[H + c];
            }
            g_si[rbase + r] = a + bedge[0];
            g_sj[rbase + r] = bb;
        }
    }
}

// ============================================================
// scores[i][j] = s_i[i] + s_j[j], diag zeroed. float4 stores.
// ============================================================
__global__ void scores_kernel(float* __restrict__ out) {
    int idx = blockIdx.x * 256 + threadIdx.x;
    int i = idx >> 10;
    int j4 = (idx & 1023) << 2;
    float si = g_si[i];
    float4 sj = *reinterpret_cast<const float4*>(&g_sj[j4]);
    float4 v = make_float4(si + sj.x, si + sj.y, si + sj.z, si + sj.w);
    int d = i - j4;
    if (d >= 0 && d < 4) ((float*)&v)[d] = 0.0f;
    reinterpret_cast<float4*>(out)[idx] = v;
}

// ============================================================
extern "C" void kernel_launch(void* const* d_in, const int* in_sizes, int n_in,
                              void* d_out, int out_size) {
    const float* X     = (const float*)d_in[0];
    const float* Adj   = (const float*)d_in[1];
    const float* We    = (const float*)d_in[2];
    const float* be    = (const float*)d_in[3];
    const float* Wl[3] = {(const float*)d_in[4], (const float*)d_in[6],
                          (const float*)d_in[8]};
    const float* bl[3] = {(const float*)d_in[5], (const float*)d_in[7],
                          (const float*)d_in[9]};
    const float* Wedge = (const float*)d_in[10];
    const float* bedge = (const float*)d_in[11];
    float* out = (float*)d_out;

    cudaFuncSetAttribute(gemm_mma_kernel,
                         cudaFuncAttributeMaxDynamicSharedMemorySize, SMEM_TOTAL);

    float *ph0 = nullptr, *ph1 = nullptr;
    cudaGetSymbolAddress((void**)&ph0, g_h0);
    cudaGetSymbolAddress((void**)&ph1, g_h1);

    convA_kernel<<<(NN * NN / 8) / 256, 256>>>(Adj);
    enc_kernel<<<NN * H / 256, 256>>>(X, We, be, ph0);

    float* hcur = ph0;
    float* hnext = ph1;
    for (int l = 0; l < 3; l++) {
        gemm_mma_kernel<<<dim3(NN / 128, SPLITK), 256, SMEM_TOTAL>>>();
        mlp_kernel<<<NN / MROWS, 256>>>(hcur, Wl[l], bl[l], hnext,
                                        (l == 2) ? 1 : 0, Wedge, bedge);
        float* t = hcur; hcur = hnext; hnext = t;
    }

    scores_kernel<<<(NN / 4) * NN / 256, 256>>>(out);
}